// round 11
// baseline (speedup 1.0000x reference)
#include <cuda_runtime.h>

// ---------------------------------------------------------------------------
// 2-layer GCN:  out = A_n * relu(BN(A_n * (x@W1))) @ W2 + b2
// A_n = D^-1/2 (A + I) D^-1/2,  deg from dst side (+ self loop)
// ---------------------------------------------------------------------------

#define NMAX  100000
#define EMAX  1600000
#define D_IN  128
#define D_H   64
#define D_OUT 32
#define BN_EPS 1e-5f

__device__ int   g_deg[NMAX];
__device__ float g_dinv[NMAX];
__device__ float g_h0[(size_t)NMAX * D_H];   // x @ W1           (pre-agg)
__device__ float g_h1[(size_t)NMAX * D_H];   // aggregated layer1
__device__ float g_h2[(size_t)NMAX * D_OUT]; // act(h1) @ W2     (pre-agg)
__device__ float g_stats[2 * D_H];           // [sum | sumsq]
__device__ float g_scale[D_H];               // gamma * invstd
__device__ float g_shift[D_H];               // beta - mean*scale

// ------------------------------ degree / norm ------------------------------

__global__ void k_zero_deg(int n) {
    int t = blockIdx.x * blockDim.x + threadIdx.x;
    if (t < n) g_deg[t] = 0;
}

__global__ void k_deg(const int* __restrict__ dst, int e) {
    int stride = gridDim.x * blockDim.x;
    for (int t = blockIdx.x * blockDim.x + threadIdx.x; t < e; t += stride)
        atomicAdd(&g_deg[dst[t]], 1);
}

__global__ void k_dinv(int n) {
    int t = blockIdx.x * blockDim.x + threadIdx.x;
    if (t < 2 * D_H) g_stats[t] = 0.f;           // reset BN stats every call
    if (t < n) g_dinv[t] = rsqrtf((float)(g_deg[t] + 1));  // +1 self-loop
}

// ------------------------------ GEMM1: h0 = x @ W1 -------------------------
// Block tile 128x64 (full N), 128 threads, each thread 8x8, K chunked by 16.

__global__ void __launch_bounds__(128) k_gemm1(const float* __restrict__ x,
                                               const float* __restrict__ W1,
                                               int n) {
    __shared__ float As[128][17];   // [m][kk], pad 17 -> conflict-free reads
    __shared__ float Bs[16][64];    // [kk][n]

    const int tid = threadIdx.x;
    const int ty  = tid >> 3;       // 0..15  (8 rows each)
    const int tx  = tid & 7;        // 0..7   (8 cols each)
    const int m0  = blockIdx.x * 128;

    float acc[8][8];
#pragma unroll
    for (int i = 0; i < 8; i++)
#pragma unroll
        for (int j = 0; j < 8; j++) acc[i][j] = 0.f;

    for (int k0 = 0; k0 < D_IN; k0 += 16) {
        // A tile: 128 rows x 16 k  (512 float4 / 128 thr = 4 each)
#pragma unroll
        for (int p = 0; p < 4; p++) {
            int q  = p * 128 + tid;
            int m  = q >> 2, kq = q & 3;
            int gm = min(m0 + m, n - 1);
            float4 v = *(const float4*)(x + (size_t)gm * D_IN + k0 + kq * 4);
            As[m][kq * 4 + 0] = v.x;
            As[m][kq * 4 + 1] = v.y;
            As[m][kq * 4 + 2] = v.z;
            As[m][kq * 4 + 3] = v.w;
        }
        // B tile: 16 x 64 (256 float4 / 128 thr = 2 each)
#pragma unroll
        for (int p = 0; p < 2; p++) {
            int q = p * 128 + tid;
            int kk = q >> 4, nq = q & 15;
            *(float4*)&Bs[kk][nq * 4] =
                *(const float4*)(W1 + (size_t)(k0 + kk) * D_H + nq * 4);
        }
        __syncthreads();

#pragma unroll
        for (int kk = 0; kk < 16; kk++) {
            float a[8], b[8];
#pragma unroll
            for (int i = 0; i < 8; i++) a[i] = As[ty * 8 + i][kk];
            float4 b0 = *(float4*)&Bs[kk][tx * 8];
            float4 b1 = *(float4*)&Bs[kk][tx * 8 + 4];
            b[0]=b0.x; b[1]=b0.y; b[2]=b0.z; b[3]=b0.w;
            b[4]=b1.x; b[5]=b1.y; b[6]=b1.z; b[7]=b1.w;
#pragma unroll
            for (int i = 0; i < 8; i++)
#pragma unroll
                for (int j = 0; j < 8; j++) acc[i][j] += a[i] * b[j];
        }
        __syncthreads();
    }

#pragma unroll
    for (int i = 0; i < 8; i++) {
        int row = m0 + ty * 8 + i;
        if (row < n) {
            float4 o0 = make_float4(acc[i][0], acc[i][1], acc[i][2], acc[i][3]);
            float4 o1 = make_float4(acc[i][4], acc[i][5], acc[i][6], acc[i][7]);
            *(float4*)(g_h0 + (size_t)row * D_H + tx * 8)     = o0;
            *(float4*)(g_h0 + (size_t)row * D_H + tx * 8 + 4) = o1;
        }
    }
}

// ---------------- prefill1: h1 = h0 * dinv^2 (self-loop, no memset) --------

__global__ void k_pre1(int n) {
    int total = n * (D_H / 4);
    int stride = gridDim.x * blockDim.x;
    for (int t = blockIdx.x * blockDim.x + threadIdx.x; t < total; t += stride) {
        int row = t >> 4;                       // 16 float4 per row
        float di = g_dinv[row];
        float w = di * di;
        float4 v = ((const float4*)g_h0)[t];
        v.x *= w; v.y *= w; v.z *= w; v.w *= w;
        ((float4*)g_h1)[t] = v;
    }
}

// ---------------- agg1: h1[dst] += h0[src] * dinv[s]*dinv[d] ----------------
// One warp per edge; lane handles 2 channels (float2 -> 256B coalesced gather)

__global__ void k_agg1(const int* __restrict__ src,
                       const int* __restrict__ dst, int e) {
    int wid  = (blockIdx.x * blockDim.x + threadIdx.x) >> 5;
    int lane = threadIdx.x & 31;
    int nw   = (gridDim.x * blockDim.x) >> 5;
    for (int ed = wid; ed < e; ed += nw) {
        int s = __ldg(src + ed);
        int d = __ldg(dst + ed);
        float w = g_dinv[s] * g_dinv[d];
        float2 v = ((const float2*)(g_h0 + (size_t)s * D_H))[lane];
        atomicAdd(&g_h1[(size_t)d * D_H + 2 * lane],     v.x * w);
        atomicAdd(&g_h1[(size_t)d * D_H + 2 * lane + 1], v.y * w);
    }
}

// ------------------------------ BN statistics ------------------------------

__global__ void k_stats(int n) {
    __shared__ float ss[D_H], sq[D_H];
    int tid = threadIdx.x;                 // 256 threads
    if (tid < D_H) { ss[tid] = 0.f; sq[tid] = 0.f; }
    __syncthreads();

    int c  = tid & (D_H - 1);
    int r0 = blockIdx.x * 4 + (tid >> 6);  // 4 row-groups per block
    int rstride = gridDim.x * 4;
    float s = 0.f, s2 = 0.f;
    for (int r = r0; r < n; r += rstride) {
        float v = g_h1[(size_t)r * D_H + c];
        s += v; s2 += v * v;
    }
    atomicAdd(&ss[c], s);
    atomicAdd(&sq[c], s2);
    __syncthreads();
    if (tid < D_H) {
        atomicAdd(&g_stats[tid], ss[tid]);
        atomicAdd(&g_stats[D_H + tid], sq[tid]);
    }
}

__global__ void k_finalize(const float* __restrict__ gamma,
                           const float* __restrict__ beta, float inv_n) {
    int c = threadIdx.x;                   // 64 threads
    float mean = g_stats[c] * inv_n;
    float var  = g_stats[D_H + c] * inv_n - mean * mean;
    float inv  = rsqrtf(var + BN_EPS);
    float sc   = gamma[c] * inv;
    g_scale[c] = sc;
    g_shift[c] = beta[c] - mean * sc;      // (b1 cancels inside BN exactly)
}

// -------------- GEMM2: h2 = relu(h1*scale + shift) @ W2 (fused BN) ---------
// Block tile 128x32, 128 threads, thread tile 4x8, whole K=64 in smem.

__global__ void __launch_bounds__(128) k_gemm2(const float* __restrict__ W2,
                                               int n) {
    __shared__ float As[128][69];          // 64 used, pad for conflict-free
    __shared__ float Bs[64][32];
    __shared__ float s_sc[D_H], s_sh[D_H];

    const int tid = threadIdx.x;
    const int m0  = blockIdx.x * 128;

    if (tid < D_H) { s_sc[tid] = g_scale[tid]; s_sh[tid] = g_shift[tid]; }
    __syncthreads();

    // A tile: one row per thread, apply BN + ReLU on load
    {
        int gm = min(m0 + tid, n - 1);
        const float4* rp = (const float4*)(g_h1 + (size_t)gm * D_H);
#pragma unroll
        for (int kq = 0; kq < 16; kq++) {
            float4 v = rp[kq];
            int k = kq * 4;
            As[tid][k + 0] = fmaxf(fmaf(v.x, s_sc[k + 0], s_sh[k + 0]), 0.f);
            As[tid][k + 1] = fmaxf(fmaf(v.y, s_sc[k + 1], s_sh[k + 1]), 0.f);
            As[tid][k + 2] = fmaxf(fmaf(v.z, s_sc[k + 2], s_sh[k + 2]), 0.f);
            As[tid][k + 3] = fmaxf(fmaf(v.w, s_sc[k + 3], s_sh[k + 3]), 0.f);
        }
    }
    // B tile: 64x32 = 512 float4 / 128 thr = 4 each
#pragma unroll
    for (int p = 0; p < 4; p++) {
        int q = p * 128 + tid;
        int kk = q >> 3, nq = q & 7;
        *(float4*)&Bs[kk][nq * 4] =
            *(const float4*)(W2 + (size_t)kk * D_OUT + nq * 4);
    }
    __syncthreads();

    const int ty = tid >> 2;               // 0..31 (4 rows each)
    const int tx = tid & 3;                // 0..3  (8 cols each)
    float acc[4][8];
#pragma unroll
    for (int i = 0; i < 4; i++)
#pragma unroll
        for (int j = 0; j < 8; j++) acc[i][j] = 0.f;

#pragma unroll
    for (int kk = 0; kk < D_H; kk++) {
        float a[4], b[8];
#pragma unroll
        for (int i = 0; i < 4; i++) a[i] = As[ty * 4 + i][kk];
        float4 b0 = *(float4*)&Bs[kk][tx * 8];
        float4 b1 = *(float4*)&Bs[kk][tx * 8 + 4];
        b[0]=b0.x; b[1]=b0.y; b[2]=b0.z; b[3]=b0.w;
        b[4]=b1.x; b[5]=b1.y; b[6]=b1.z; b[7]=b1.w;
#pragma unroll
        for (int i = 0; i < 4; i++)
#pragma unroll
            for (int j = 0; j < 8; j++) acc[i][j] += a[i] * b[j];
    }

#pragma unroll
    for (int i = 0; i < 4; i++) {
        int row = m0 + ty * 4 + i;
        if (row < n) {
            float4 o0 = make_float4(acc[i][0], acc[i][1], acc[i][2], acc[i][3]);
            float4 o1 = make_float4(acc[i][4], acc[i][5], acc[i][6], acc[i][7]);
            *(float4*)(g_h2 + (size_t)row * D_OUT + tx * 8)     = o0;
            *(float4*)(g_h2 + (size_t)row * D_OUT + tx * 8 + 4) = o1;
        }
    }
}

// ---------- prefill2: out = h2 * dinv^2 + b2 (self-loop + bias) -------------

__global__ void k_pre2(int n, float* __restrict__ out,
                       const float* __restrict__ b2) {
    int total = n * (D_OUT / 4);
    int stride = gridDim.x * blockDim.x;
    for (int t = blockIdx.x * blockDim.x + threadIdx.x; t < total; t += stride) {
        int row = t >> 3;                   // 8 float4 per row
        int cq  = t & 7;
        float di = g_dinv[row];
        float w = di * di;
        float4 v = ((const float4*)g_h2)[t];
        float4 b = ((const float4*)b2)[cq];
        v.x = fmaf(v.x, w, b.x);
        v.y = fmaf(v.y, w, b.y);
        v.z = fmaf(v.z, w, b.z);
        v.w = fmaf(v.w, w, b.w);
        ((float4*)out)[t] = v;
    }
}

// ---------------- agg2: out[dst] += h2[src] * dinv[s]*dinv[d] ---------------
// Half-warp per edge; lane handles float2 (128B coalesced gather per edge)

__global__ void k_agg2(const int* __restrict__ src,
                       const int* __restrict__ dst, int e,
                       float* __restrict__ out) {
    int hw = (blockIdx.x * blockDim.x + threadIdx.x) >> 4;
    int j  = threadIdx.x & 15;
    int nh = (gridDim.x * blockDim.x) >> 4;
    for (int ed = hw; ed < e; ed += nh) {
        int s = __ldg(src + ed);
        int d = __ldg(dst + ed);
        float w = g_dinv[s] * g_dinv[d];
        float2 v = ((const float2*)(g_h2 + (size_t)s * D_OUT))[j];
        atomicAdd(&out[(size_t)d * D_OUT + 2 * j],     v.x * w);
        atomicAdd(&out[(size_t)d * D_OUT + 2 * j + 1], v.y * w);
    }
}

// ---------------------------------------------------------------------------

extern "C" void kernel_launch(void* const* d_in, const int* in_sizes, int n_in,
                              void* d_out, int out_size) {
    const float* x     = (const float*)d_in[0];
    const int*   edge  = (const int*)  d_in[1];
    const float* W1    = (const float*)d_in[2];
    // d_in[3] = b1 : cancels exactly inside batchnorm, unused
    const float* gamma = (const float*)d_in[4];
    const float* beta  = (const float*)d_in[5];
    const float* W2    = (const float*)d_in[6];
    const float* b2    = (const float*)d_in[7];
    float* out = (float*)d_out;

    const int n = in_sizes[0] / D_IN;
    const int e = in_sizes[1] / 2;
    const int* src = edge;       // edge_index[0]
    const int* dst = edge + e;   // edge_index[1]

    // degrees + symmetric norm
    k_zero_deg<<<(n + 255) / 256, 256>>>(n);
    k_deg<<<2048, 256>>>(dst, e);
    k_dinv<<<(n + 255) / 256, 256>>>(n);

    // layer 1
    k_gemm1<<<(n + 127) / 128, 128>>>(x, W1, n);
    k_pre1<<<2048, 256>>>(n);
    k_agg1<<<4096, 256>>>(src, dst, e);

    // batchnorm stats
    k_stats<<<256, 256>>>(n);
    k_finalize<<<1, 64>>>(gamma, beta, 1.0f / (float)n);

    // layer 2 (BN + ReLU fused into GEMM2 A-load)
    k_gemm2<<<(n + 127) / 128, 128>>>(W2, n);
    k_pre2<<<2048, 256>>>(n, out, b2);
    k_agg2<<<4096, 256>>>(src, dst, e, out);
}

// round 12
// speedup vs baseline: 1.4825x; 1.4825x over previous
#include <cuda_runtime.h>

// ---------------------------------------------------------------------------
// 2-layer GCN:  out = A_n * relu(BN(A_n * (x@W1))) @ W2 + b2
// A_n = D^-1/2 (A + I) D^-1/2
//
// R12 strategy: CSR-bucketed GATHER aggregation (no f32 atomics on features).
//   - per-node region allocation via warp-aggregated atomicAdd (no scan/sort)
//   - scatter edges into csrc buckets
//   - warp-per-node gather with unroll-4 neighbor batching (L2-resident rows)
//   - BN stats fused into agg1 epilogue; self-loop & b2 fused into gathers
// ---------------------------------------------------------------------------

#define NMAX  100000
#define EMAX  1600000
#define D_IN  128
#define D_H   64
#define D_OUT 32
#define BN_EPS 1e-5f

__device__ int   g_deg[NMAX];
__device__ int   g_rowptr[NMAX];
__device__ int   g_cursor[NMAX];
__device__ int   g_csrc[EMAX];
__device__ int   g_total;
__device__ float g_dinv[NMAX];
__device__ float g_h0[(size_t)NMAX * D_H];   // x @ W1           (pre-agg)
__device__ float g_h1[(size_t)NMAX * D_H];   // aggregated layer1
__device__ float g_h2[(size_t)NMAX * D_OUT]; // act(h1) @ W2     (pre-agg)
__device__ float g_stats[2 * D_H];           // [sum | sumsq]
__device__ float g_scale[D_H];               // gamma * invstd
__device__ float g_shift[D_H];               // beta - mean*scale

// ------------------------------ degree / norm ------------------------------

__global__ void k_zero_deg(int n) {
    int t = blockIdx.x * blockDim.x + threadIdx.x;
    if (t < n) g_deg[t] = 0;
    if (t == 0) g_total = 0;
}

__global__ void k_deg(const int* __restrict__ dst, int e) {
    int stride = gridDim.x * blockDim.x;
    for (int t = blockIdx.x * blockDim.x + threadIdx.x; t < e; t += stride)
        atomicAdd(&g_deg[dst[t]], 1);
}

__global__ void k_dinv(int n) {
    int t = blockIdx.x * blockDim.x + threadIdx.x;
    if (t < 2 * D_H) g_stats[t] = 0.f;           // reset BN stats every call
    if (t < n) g_dinv[t] = rsqrtf((float)(g_deg[t] + 1));  // +1 self-loop
}

// --------------- CSR region allocation (order-free, no scan) ---------------
// Each node gets a contiguous region of size deg[node] in g_csrc. Region
// order across nodes is irrelevant for the gather, so a warp-aggregated
// atomic bump on one counter suffices (3125 single-addr atomics total).

__global__ void k_alloc(int n) {
    int t    = blockIdx.x * blockDim.x + threadIdx.x;
    int lane = threadIdx.x & 31;
    int d    = (t < n) ? g_deg[t] : 0;
    // warp-inclusive scan of d
    int sc = d;
#pragma unroll
    for (int o = 1; o < 32; o <<= 1) {
        int v = __shfl_up_sync(0xFFFFFFFFu, sc, o);
        if (lane >= o) sc += v;
    }
    int tot  = __shfl_sync(0xFFFFFFFFu, sc, 31);
    int base = 0;
    if (lane == 31) base = atomicAdd(&g_total, tot);
    base = __shfl_sync(0xFFFFFFFFu, base, 31);
    int excl = base + sc - d;
    if (t < n) { g_rowptr[t] = excl; g_cursor[t] = excl; }
}

__global__ void k_scatter(const int* __restrict__ src,
                          const int* __restrict__ dst, int e) {
    int stride = gridDim.x * blockDim.x;
    for (int t = blockIdx.x * blockDim.x + threadIdx.x; t < e; t += stride) {
        int d = dst[t];
        int pos = atomicAdd(&g_cursor[d], 1);
        g_csrc[pos] = src[t];
    }
}

// ------------------------------ GEMM1: h0 = x @ W1 -------------------------
// Block tile 128x64 (full N), 128 threads, each thread 8x8, K chunked by 16.

__global__ void __launch_bounds__(128) k_gemm1(const float* __restrict__ x,
                                               const float* __restrict__ W1,
                                               int n) {
    __shared__ float As[128][17];   // [m][kk], pad 17 -> conflict-free reads
    __shared__ float Bs[16][64];    // [kk][n]

    const int tid = threadIdx.x;
    const int ty  = tid >> 3;       // 0..15  (8 rows each)
    const int tx  = tid & 7;        // 0..7   (8 cols each)
    const int m0  = blockIdx.x * 128;

    float acc[8][8];
#pragma unroll
    for (int i = 0; i < 8; i++)
#pragma unroll
        for (int j = 0; j < 8; j++) acc[i][j] = 0.f;

    for (int k0 = 0; k0 < D_IN; k0 += 16) {
#pragma unroll
        for (int p = 0; p < 4; p++) {
            int q  = p * 128 + tid;
            int m  = q >> 2, kq = q & 3;
            int gm = min(m0 + m, n - 1);
            float4 v = *(const float4*)(x + (size_t)gm * D_IN + k0 + kq * 4);
            As[m][kq * 4 + 0] = v.x;
            As[m][kq * 4 + 1] = v.y;
            As[m][kq * 4 + 2] = v.z;
            As[m][kq * 4 + 3] = v.w;
        }
#pragma unroll
        for (int p = 0; p < 2; p++) {
            int q = p * 128 + tid;
            int kk = q >> 4, nq = q & 15;
            *(float4*)&Bs[kk][nq * 4] =
                *(const float4*)(W1 + (size_t)(k0 + kk) * D_H + nq * 4);
        }
        __syncthreads();

#pragma unroll
        for (int kk = 0; kk < 16; kk++) {
            float a[8], b[8];
#pragma unroll
            for (int i = 0; i < 8; i++) a[i] = As[ty * 8 + i][kk];
            float4 b0 = *(float4*)&Bs[kk][tx * 8];
            float4 b1 = *(float4*)&Bs[kk][tx * 8 + 4];
            b[0]=b0.x; b[1]=b0.y; b[2]=b0.z; b[3]=b0.w;
            b[4]=b1.x; b[5]=b1.y; b[6]=b1.z; b[7]=b1.w;
#pragma unroll
            for (int i = 0; i < 8; i++)
#pragma unroll
                for (int j = 0; j < 8; j++) acc[i][j] += a[i] * b[j];
        }
        __syncthreads();
    }

#pragma unroll
    for (int i = 0; i < 8; i++) {
        int row = m0 + ty * 8 + i;
        if (row < n) {
            float4 o0 = make_float4(acc[i][0], acc[i][1], acc[i][2], acc[i][3]);
            float4 o1 = make_float4(acc[i][4], acc[i][5], acc[i][6], acc[i][7]);
            *(float4*)(g_h0 + (size_t)row * D_H + tx * 8)     = o0;
            *(float4*)(g_h0 + (size_t)row * D_H + tx * 8 + 4) = o1;
        }
    }
}

// ---- agg1 (gather): h1[d] = dinv[d] * (h0[d]*dinv[d] + sum h0[s]*dinv[s])
// Warp per node (grid-stride), lane handles 2 channels. BN stats fused:
// register accumulation -> smem -> 128 global atomics per block.

__global__ void __launch_bounds__(256) k_agg1(int n) {
    __shared__ float ss[D_H], sq[D_H];
    const int tid = threadIdx.x;
    if (tid < D_H) { ss[tid] = 0.f; sq[tid] = 0.f; }
    __syncthreads();

    const int lane = tid & 31;
    const int wid  = (blockIdx.x * blockDim.x + tid) >> 5;
    const int nw   = (gridDim.x * blockDim.x) >> 5;

    float s0 = 0.f, s1 = 0.f, q0 = 0.f, q1 = 0.f;

    for (int row = wid; row < n; row += nw) {
        float di = g_dinv[row];
        float2 h = ((const float2*)(g_h0 + (size_t)row * D_H))[lane];
        float ax = h.x * di, ay = h.y * di;   // self-loop term (pre dinv[d])

        int start = g_rowptr[row];
        int end   = start + g_deg[row];
        int j = start;
        for (; j + 4 <= end; j += 4) {
            int sa = g_csrc[j],     sb = g_csrc[j + 1];
            int sc = g_csrc[j + 2], sd = g_csrc[j + 3];
            float wa = g_dinv[sa], wb = g_dinv[sb];
            float wc = g_dinv[sc], wd = g_dinv[sd];
            float2 va = ((const float2*)(g_h0 + (size_t)sa * D_H))[lane];
            float2 vb = ((const float2*)(g_h0 + (size_t)sb * D_H))[lane];
            float2 vc = ((const float2*)(g_h0 + (size_t)sc * D_H))[lane];
            float2 vd = ((const float2*)(g_h0 + (size_t)sd * D_H))[lane];
            ax += va.x * wa + vb.x * wb + vc.x * wc + vd.x * wd;
            ay += va.y * wa + vb.y * wb + vc.y * wc + vd.y * wd;
        }
        for (; j < end; j++) {
            int s = g_csrc[j];
            float w = g_dinv[s];
            float2 v = ((const float2*)(g_h0 + (size_t)s * D_H))[lane];
            ax += v.x * w;
            ay += v.y * w;
        }
        ax *= di; ay *= di;
        ((float2*)(g_h1 + (size_t)row * D_H))[lane] = make_float2(ax, ay);

        s0 += ax; s1 += ay;
        q0 += ax * ax; q1 += ay * ay;
    }

    atomicAdd(&ss[2 * lane],     s0);
    atomicAdd(&ss[2 * lane + 1], s1);
    atomicAdd(&sq[2 * lane],     q0);
    atomicAdd(&sq[2 * lane + 1], q1);
    __syncthreads();
    if (tid < D_H) {
        atomicAdd(&g_stats[tid],       ss[tid]);
        atomicAdd(&g_stats[D_H + tid], sq[tid]);
    }
}

// ------------------------------ BN finalize --------------------------------

__global__ void k_finalize(const float* __restrict__ gamma,
                           const float* __restrict__ beta, float inv_n) {
    int c = threadIdx.x;                   // 64 threads
    float mean = g_stats[c] * inv_n;
    float var  = g_stats[D_H + c] * inv_n - mean * mean;
    float inv  = rsqrtf(var + BN_EPS);
    float sc   = gamma[c] * inv;
    g_scale[c] = sc;
    g_shift[c] = beta[c] - mean * sc;      // (b1 cancels inside BN exactly)
}

// -------------- GEMM2: h2 = relu(h1*scale + shift) @ W2 (fused BN) ---------

__global__ void __launch_bounds__(128) k_gemm2(const float* __restrict__ W2,
                                               int n) {
    __shared__ float As[128][69];          // 64 used, pad for conflict-free
    __shared__ float Bs[64][32];
    __shared__ float s_sc[D_H], s_sh[D_H];

    const int tid = threadIdx.x;
    const int m0  = blockIdx.x * 128;

    if (tid < D_H) { s_sc[tid] = g_scale[tid]; s_sh[tid] = g_shift[tid]; }
    __syncthreads();

    {
        int gm = min(m0 + tid, n - 1);
        const float4* rp = (const float4*)(g_h1 + (size_t)gm * D_H);
#pragma unroll
        for (int kq = 0; kq < 16; kq++) {
            float4 v = rp[kq];
            int k = kq * 4;
            As[tid][k + 0] = fmaxf(fmaf(v.x, s_sc[k + 0], s_sh[k + 0]), 0.f);
            As[tid][k + 1] = fmaxf(fmaf(v.y, s_sc[k + 1], s_sh[k + 1]), 0.f);
            As[tid][k + 2] = fmaxf(fmaf(v.z, s_sc[k + 2], s_sh[k + 2]), 0.f);
            As[tid][k + 3] = fmaxf(fmaf(v.w, s_sc[k + 3], s_sh[k + 3]), 0.f);
        }
    }
#pragma unroll
    for (int p = 0; p < 4; p++) {
        int q = p * 128 + tid;
        int kk = q >> 3, nq = q & 7;
        *(float4*)&Bs[kk][nq * 4] =
            *(const float4*)(W2 + (size_t)kk * D_OUT + nq * 4);
    }
    __syncthreads();

    const int ty = tid >> 2;               // 0..31 (4 rows each)
    const int tx = tid & 3;                // 0..3  (8 cols each)
    float acc[4][8];
#pragma unroll
    for (int i = 0; i < 4; i++)
#pragma unroll
        for (int j = 0; j < 8; j++) acc[i][j] = 0.f;

#pragma unroll
    for (int kk = 0; kk < D_H; kk++) {
        float a[4], b[8];
#pragma unroll
        for (int i = 0; i < 4; i++) a[i] = As[ty * 4 + i][kk];
        float4 b0 = *(float4*)&Bs[kk][tx * 8];
        float4 b1 = *(float4*)&Bs[kk][tx * 8 + 4];
        b[0]=b0.x; b[1]=b0.y; b[2]=b0.z; b[3]=b0.w;
        b[4]=b1.x; b[5]=b1.y; b[6]=b1.z; b[7]=b1.w;
#pragma unroll
        for (int i = 0; i < 4; i++)
#pragma unroll
            for (int j = 0; j < 8; j++) acc[i][j] += a[i] * b[j];
    }

#pragma unroll
    for (int i = 0; i < 4; i++) {
        int row = m0 + ty * 4 + i;
        if (row < n) {
            float4 o0 = make_float4(acc[i][0], acc[i][1], acc[i][2], acc[i][3]);
            float4 o1 = make_float4(acc[i][4], acc[i][5], acc[i][6], acc[i][7]);
            *(float4*)(g_h2 + (size_t)row * D_OUT + tx * 8)     = o0;
            *(float4*)(g_h2 + (size_t)row * D_OUT + tx * 8 + 4) = o1;
        }
    }
}

// ---- agg2 (gather): out[d] = dinv[d]*(h2[d]*dinv[d] + sum h2[s]*dinv[s]) + b2
// Warp per node, lane = channel (D_OUT = 32).

__global__ void __launch_bounds__(256) k_agg2(int n, float* __restrict__ out,
                                              const float* __restrict__ b2) {
    const int lane = threadIdx.x & 31;
    const int wid  = (blockIdx.x * blockDim.x + threadIdx.x) >> 5;
    const int nw   = (gridDim.x * blockDim.x) >> 5;
    const float bb = b2[lane];

    for (int row = wid; row < n; row += nw) {
        float di = g_dinv[row];
        float acc = g_h2[(size_t)row * D_OUT + lane] * di;  // self-loop

        int start = g_rowptr[row];
        int end   = start + g_deg[row];
        int j = start;
        for (; j + 4 <= end; j += 4) {
            int sa = g_csrc[j],     sb = g_csrc[j + 1];
            int sc = g_csrc[j + 2], sd = g_csrc[j + 3];
            float wa = g_dinv[sa], wb = g_dinv[sb];
            float wc = g_dinv[sc], wd = g_dinv[sd];
            float va = g_h2[(size_t)sa * D_OUT + lane];
            float vb = g_h2[(size_t)sb * D_OUT + lane];
            float vc = g_h2[(size_t)sc * D_OUT + lane];
            float vd = g_h2[(size_t)sd * D_OUT + lane];
            acc += va * wa + vb * wb + vc * wc + vd * wd;
        }
        for (; j < end; j++) {
            int s = g_csrc[j];
            acc += g_h2[(size_t)s * D_OUT + lane] * g_dinv[s];
        }
        out[(size_t)row * D_OUT + lane] = acc * di + bb;
    }
}

// ---------------------------------------------------------------------------

extern "C" void kernel_launch(void* const* d_in, const int* in_sizes, int n_in,
                              void* d_out, int out_size) {
    const float* x     = (const float*)d_in[0];
    const int*   edge  = (const int*)  d_in[1];
    const float* W1    = (const float*)d_in[2];
    // d_in[3] = b1 : cancels exactly inside batchnorm, unused
    const float* gamma = (const float*)d_in[4];
    const float* beta  = (const float*)d_in[5];
    const float* W2    = (const float*)d_in[6];
    const float* b2    = (const float*)d_in[7];
    float* out = (float*)d_out;

    const int n = in_sizes[0] / D_IN;
    const int e = in_sizes[1] / 2;
    const int* src = edge;       // edge_index[0]
    const int* dst = edge + e;   // edge_index[1]

    // degrees + symmetric norm
    k_zero_deg<<<(n + 255) / 256, 256>>>(n);
    k_deg<<<2048, 256>>>(dst, e);
    k_dinv<<<(n + 255) / 256, 256>>>(n);

    // CSR buckets (order-free allocation, then scatter)
    k_alloc<<<(n + 255) / 256, 256>>>(n);
    k_scatter<<<2048, 256>>>(src, dst, e);

    // layer 1
    k_gemm1<<<(n + 127) / 128, 128>>>(x, W1, n);
    k_agg1<<<1184, 256>>>(n);                 // gather + fused BN stats

    k_finalize<<<1, 64>>>(gamma, beta, 1.0f / (float)n);

    // layer 2 (BN + ReLU fused into GEMM2 A-load)
    k_gemm2<<<(n + 127) / 128, 128>>>(W2, n);
    k_agg2<<<1184, 256>>>(n, out, b2);        // gather + fused b2
}

// round 13
// speedup vs baseline: 1.7696x; 1.1937x over previous
#include <cuda_runtime.h>

// ---------------------------------------------------------------------------
// 2-layer GCN:  out = A_n * relu(BN(A_n * (x@W1))) @ W2 + b2
// A_n = D^-1/2 (A + I) D^-1/2
//
// R13: f32x2 packed-FMA GEMMs (2x fp32 roofline), dinv pre-scaled features
//      (pure-add gather inner loops), dinv+alloc fused.
// ---------------------------------------------------------------------------

#define NMAX  100000
#define EMAX  1600000
#define D_IN  128
#define D_H   64
#define D_OUT 32
#define BN_EPS 1e-5f

__device__ int   g_deg[NMAX];
__device__ int   g_rowptr[NMAX];
__device__ int   g_cursor[NMAX];
__device__ int   g_csrc[EMAX];
__device__ int   g_total;
__device__ float g_dinv[NMAX];
__device__ float g_h0[(size_t)NMAX * D_H];   // (x @ W1) * dinv[row]
__device__ float g_h1[(size_t)NMAX * D_H];   // aggregated layer1
__device__ float g_h2[(size_t)NMAX * D_OUT]; // (act(h1) @ W2) * dinv[row]
__device__ float g_stats[2 * D_H];           // [sum | sumsq]
__device__ float g_scale[D_H];               // gamma * invstd
__device__ float g_shift[D_H];               // beta - mean*scale

// ---- packed f32x2 helpers (Blackwell sm_103a) ----
#define FMA2(acc, a, b) \
    asm("fma.rn.f32x2 %0, %1, %2, %0;" : "+l"(acc) : "l"(a), "l"(b))
#define PK2(d, lo, hi) \
    asm("mov.b64 %0, {%1, %2};" : "=l"(d) : "f"(lo), "f"(hi))
#define UPK2(lo, hi, v) \
    asm("mov.b64 {%0, %1}, %2;" : "=f"(lo), "=f"(hi) : "l"(v))

// ------------------------------ degree / norm ------------------------------

__global__ void k_zero_deg(int n) {
    int t = blockIdx.x * blockDim.x + threadIdx.x;
    if (t < n) g_deg[t] = 0;
    if (t == 0) g_total = 0;
}

__global__ void k_deg(const int* __restrict__ dst, int e) {
    int stride = gridDim.x * blockDim.x;
    for (int t = blockIdx.x * blockDim.x + threadIdx.x; t < e; t += stride)
        atomicAdd(&g_deg[dst[t]], 1);
}

// ---- fused: dinv + BN-stat reset + CSR region allocation (order-free) ----
// Region order across nodes is irrelevant for the gather, so a warp-
// aggregated atomic bump on one counter replaces a device-wide scan.

__global__ void k_dinv_alloc(int n) {
    int t    = blockIdx.x * blockDim.x + threadIdx.x;
    int lane = threadIdx.x & 31;
    if (t < 2 * D_H) g_stats[t] = 0.f;
    int d = (t < n) ? g_deg[t] : 0;
    if (t < n) g_dinv[t] = rsqrtf((float)(d + 1));   // +1 self-loop
    // warp-inclusive scan of d
    int sc = d;
#pragma unroll
    for (int o = 1; o < 32; o <<= 1) {
        int v = __shfl_up_sync(0xFFFFFFFFu, sc, o);
        if (lane >= o) sc += v;
    }
    int tot  = __shfl_sync(0xFFFFFFFFu, sc, 31);
    int base = 0;
    if (lane == 31) base = atomicAdd(&g_total, tot);
    base = __shfl_sync(0xFFFFFFFFu, base, 31);
    int excl = base + sc - d;
    if (t < n) { g_rowptr[t] = excl; g_cursor[t] = excl; }
}

__global__ void k_scatter(const int* __restrict__ src,
                          const int* __restrict__ dst, int e) {
    int stride = gridDim.x * blockDim.x;
    for (int t = blockIdx.x * blockDim.x + threadIdx.x; t < e; t += stride) {
        int d = dst[t];
        int pos = atomicAdd(&g_cursor[d], 1);
        g_csrc[pos] = src[t];
    }
}

// ------------------- GEMM1: h0 = (x @ W1) * dinv[row] ----------------------
// Block tile 128x64, 128 threads, thread tile 8x8 via 4 packed f32x2 accs.

__global__ void __launch_bounds__(128) k_gemm1(const float* __restrict__ x,
                                               const float* __restrict__ W1,
                                               int n) {
    __shared__ float As[128][17];   // [m][kk], pad -> conflict-free reads
    __shared__ float Bs[16][64];    // [kk][n]

    const int tid = threadIdx.x;
    const int ty  = tid >> 3;       // 0..15  (8 rows each)
    const int tx  = tid & 7;        // 0..7   (8 cols each)
    const int m0  = blockIdx.x * 128;

    unsigned long long acc[8][4];   // 8 rows x 4 col-pairs (f32x2)
#pragma unroll
    for (int i = 0; i < 8; i++)
#pragma unroll
        for (int j = 0; j < 4; j++) acc[i][j] = 0ull;

    for (int k0 = 0; k0 < D_IN; k0 += 16) {
#pragma unroll
        for (int p = 0; p < 4; p++) {
            int q  = p * 128 + tid;
            int m  = q >> 2, kq = q & 3;
            int gm = min(m0 + m, n - 1);
            float4 v = *(const float4*)(x + (size_t)gm * D_IN + k0 + kq * 4);
            As[m][kq * 4 + 0] = v.x;
            As[m][kq * 4 + 1] = v.y;
            As[m][kq * 4 + 2] = v.z;
            As[m][kq * 4 + 3] = v.w;
        }
#pragma unroll
        for (int p = 0; p < 2; p++) {
            int q = p * 128 + tid;
            int kk = q >> 4, nq = q & 15;
            *(float4*)&Bs[kk][nq * 4] =
                *(const float4*)(W1 + (size_t)(k0 + kk) * D_H + nq * 4);
        }
        __syncthreads();

#pragma unroll
        for (int kk = 0; kk < 16; kk++) {
            float4 b0 = *(float4*)&Bs[kk][tx * 8];
            float4 b1 = *(float4*)&Bs[kk][tx * 8 + 4];
            unsigned long long bp[4];
            PK2(bp[0], b0.x, b0.y);
            PK2(bp[1], b0.z, b0.w);
            PK2(bp[2], b1.x, b1.y);
            PK2(bp[3], b1.z, b1.w);
#pragma unroll
            for (int i = 0; i < 8; i++) {
                float a = As[ty * 8 + i][kk];
                unsigned long long ap;
                PK2(ap, a, a);
#pragma unroll
                for (int j = 0; j < 4; j++) FMA2(acc[i][j], ap, bp[j]);
            }
        }
        __syncthreads();
    }

#pragma unroll
    for (int i = 0; i < 8; i++) {
        int row = m0 + ty * 8 + i;
        if (row < n) {
            float di = g_dinv[row];
            float f[8];
#pragma unroll
            for (int j = 0; j < 4; j++) {
                float lo, hi;
                UPK2(lo, hi, acc[i][j]);
                f[2 * j]     = lo * di;
                f[2 * j + 1] = hi * di;
            }
            *(float4*)(g_h0 + (size_t)row * D_H + tx * 8) =
                make_float4(f[0], f[1], f[2], f[3]);
            *(float4*)(g_h0 + (size_t)row * D_H + tx * 8 + 4) =
                make_float4(f[4], f[5], f[6], f[7]);
        }
    }
}

// ---- agg1 (gather): h1[d] = dinv[d] * (h0s[d] + sum h0s[s])   (pure adds)
// Warp per node, lane = 2 channels. BN stats fused in epilogue.

__global__ void __launch_bounds__(256) k_agg1(int n) {
    __shared__ float ss[D_H], sq[D_H];
    const int tid = threadIdx.x;
    if (tid < D_H) { ss[tid] = 0.f; sq[tid] = 0.f; }
    __syncthreads();

    const int lane = tid & 31;
    const int wid  = (blockIdx.x * blockDim.x + tid) >> 5;
    const int nw   = (gridDim.x * blockDim.x) >> 5;

    float s0 = 0.f, s1 = 0.f, q0 = 0.f, q1 = 0.f;

    for (int row = wid; row < n; row += nw) {
        float di = g_dinv[row];
        float2 h = ((const float2*)(g_h0 + (size_t)row * D_H))[lane];
        float ax = h.x, ay = h.y;           // self-loop term (h0s = h0*dinv)

        int start = g_rowptr[row];
        int end   = start + g_deg[row];
        int j = start;
        for (; j + 4 <= end; j += 4) {
            int sa = g_csrc[j],     sb = g_csrc[j + 1];
            int sc = g_csrc[j + 2], sd = g_csrc[j + 3];
            float2 va = ((const float2*)(g_h0 + (size_t)sa * D_H))[lane];
            float2 vb = ((const float2*)(g_h0 + (size_t)sb * D_H))[lane];
            float2 vc = ((const float2*)(g_h0 + (size_t)sc * D_H))[lane];
            float2 vd = ((const float2*)(g_h0 + (size_t)sd * D_H))[lane];
            ax += va.x + vb.x + vc.x + vd.x;
            ay += va.y + vb.y + vc.y + vd.y;
        }
        for (; j < end; j++) {
            int s = g_csrc[j];
            float2 v = ((const float2*)(g_h0 + (size_t)s * D_H))[lane];
            ax += v.x;
            ay += v.y;
        }
        ax *= di; ay *= di;
        ((float2*)(g_h1 + (size_t)row * D_H))[lane] = make_float2(ax, ay);

        s0 += ax; s1 += ay;
        q0 += ax * ax; q1 += ay * ay;
    }

    atomicAdd(&ss[2 * lane],     s0);
    atomicAdd(&ss[2 * lane + 1], s1);
    atomicAdd(&sq[2 * lane],     q0);
    atomicAdd(&sq[2 * lane + 1], q1);
    __syncthreads();
    if (tid < D_H) {
        atomicAdd(&g_stats[tid],       ss[tid]);
        atomicAdd(&g_stats[D_H + tid], sq[tid]);
    }
}

// ------------------------------ BN finalize --------------------------------

__global__ void k_finalize(const float* __restrict__ gamma,
                           const float* __restrict__ beta, float inv_n) {
    int c = threadIdx.x;                   // 64 threads
    float mean = g_stats[c] * inv_n;
    float var  = g_stats[D_H + c] * inv_n - mean * mean;
    float inv  = rsqrtf(var + BN_EPS);
    float sc   = gamma[c] * inv;
    g_scale[c] = sc;
    g_shift[c] = beta[c] - mean * sc;      // (b1 cancels inside BN exactly)
}

// ------- GEMM2: h2 = (relu(h1*scale + shift) @ W2) * dinv[row] -------------
// Block 128x32, 128 threads, thread tile 4x8 via 4 packed f32x2 accs.

__global__ void __launch_bounds__(128) k_gemm2(const float* __restrict__ W2,
                                               int n) {
    __shared__ float As[128][69];          // 64 used, pad
    __shared__ float Bs[64][32];
    __shared__ float s_sc[D_H], s_sh[D_H];

    const int tid = threadIdx.x;
    const int m0  = blockIdx.x * 128;

    if (tid < D_H) { s_sc[tid] = g_scale[tid]; s_sh[tid] = g_shift[tid]; }
    __syncthreads();

    {
        int gm = min(m0 + tid, n - 1);
        const float4* rp = (const float4*)(g_h1 + (size_t)gm * D_H);
#pragma unroll
        for (int kq = 0; kq < 16; kq++) {
            float4 v = rp[kq];
            int k = kq * 4;
            As[tid][k + 0] = fmaxf(fmaf(v.x, s_sc[k + 0], s_sh[k + 0]), 0.f);
            As[tid][k + 1] = fmaxf(fmaf(v.y, s_sc[k + 1], s_sh[k + 1]), 0.f);
            As[tid][k + 2] = fmaxf(fmaf(v.z, s_sc[k + 2], s_sh[k + 2]), 0.f);
            As[tid][k + 3] = fmaxf(fmaf(v.w, s_sc[k + 3], s_sh[k + 3]), 0.f);
        }
    }
#pragma unroll
    for (int p = 0; p < 4; p++) {
        int q = p * 128 + tid;
        int kk = q >> 3, nq = q & 7;
        *(float4*)&Bs[kk][nq * 4] =
            *(const float4*)(W2 + (size_t)kk * D_OUT + nq * 4);
    }
    __syncthreads();

    const int ty = tid >> 2;               // 0..31 (4 rows each)
    const int tx = tid & 3;                // 0..3  (8 cols each)
    unsigned long long acc[4][4];
#pragma unroll
    for (int i = 0; i < 4; i++)
#pragma unroll
        for (int j = 0; j < 4; j++) acc[i][j] = 0ull;

#pragma unroll
    for (int kk = 0; kk < D_H; kk++) {
        float4 b0 = *(float4*)&Bs[kk][tx * 8];
        float4 b1 = *(float4*)&Bs[kk][tx * 8 + 4];
        unsigned long long bp[4];
        PK2(bp[0], b0.x, b0.y);
        PK2(bp[1], b0.z, b0.w);
        PK2(bp[2], b1.x, b1.y);
        PK2(bp[3], b1.z, b1.w);
#pragma unroll
        for (int i = 0; i < 4; i++) {
            float a = As[ty * 4 + i][kk];
            unsigned long long ap;
            PK2(ap, a, a);
#pragma unroll
            for (int j = 0; j < 4; j++) FMA2(acc[i][j], ap, bp[j]);
        }
    }

#pragma unroll
    for (int i = 0; i < 4; i++) {
        int row = m0 + ty * 4 + i;
        if (row < n) {
            float di = g_dinv[row];
            float f[8];
#pragma unroll
            for (int j = 0; j < 4; j++) {
                float lo, hi;
                UPK2(lo, hi, acc[i][j]);
                f[2 * j]     = lo * di;
                f[2 * j + 1] = hi * di;
            }
            *(float4*)(g_h2 + (size_t)row * D_OUT + tx * 8) =
                make_float4(f[0], f[1], f[2], f[3]);
            *(float4*)(g_h2 + (size_t)row * D_OUT + tx * 8 + 4) =
                make_float4(f[4], f[5], f[6], f[7]);
        }
    }
}

// ---- agg2 (gather): out[d] = dinv[d]*(h2s[d] + sum h2s[s]) + b2 -----------

__global__ void __launch_bounds__(256) k_agg2(int n, float* __restrict__ out,
                                              const float* __restrict__ b2) {
    const int lane = threadIdx.x & 31;
    const int wid  = (blockIdx.x * blockDim.x + threadIdx.x) >> 5;
    const int nw   = (gridDim.x * blockDim.x) >> 5;
    const float bb = b2[lane];

    for (int row = wid; row < n; row += nw) {
        float di = g_dinv[row];
        float acc = g_h2[(size_t)row * D_OUT + lane];   // self-loop (scaled)

        int start = g_rowptr[row];
        int end   = start + g_deg[row];
        int j = start;
        for (; j + 4 <= end; j += 4) {
            int sa = g_csrc[j],     sb = g_csrc[j + 1];
            int sc = g_csrc[j + 2], sd = g_csrc[j + 3];
            float va = g_h2[(size_t)sa * D_OUT + lane];
            float vb = g_h2[(size_t)sb * D_OUT + lane];
            float vc = g_h2[(size_t)sc * D_OUT + lane];
            float vd = g_h2[(size_t)sd * D_OUT + lane];
            acc += va + vb + vc + vd;
        }
        for (; j < end; j++)
            acc += g_h2[(size_t)g_csrc[j] * D_OUT + lane];

        out[(size_t)row * D_OUT + lane] = acc * di + bb;
    }
}

// ---------------------------------------------------------------------------

extern "C" void kernel_launch(void* const* d_in, const int* in_sizes, int n_in,
                              void* d_out, int out_size) {
    const float* x     = (const float*)d_in[0];
    const int*   edge  = (const int*)  d_in[1];
    const float* W1    = (const float*)d_in[2];
    // d_in[3] = b1 : cancels exactly inside batchnorm, unused
    const float* gamma = (const float*)d_in[4];
    const float* beta  = (const float*)d_in[5];
    const float* W2    = (const float*)d_in[6];
    const float* b2    = (const float*)d_in[7];
    float* out = (float*)d_out;

    const int n = in_sizes[0] / D_IN;
    const int e = in_sizes[1] / 2;
    const int* src = edge;       // edge_index[0]
    const int* dst = edge + e;   // edge_index[1]

    // degrees + norm + CSR buckets
    k_zero_deg<<<(n + 255) / 256, 256>>>(n);
    k_deg<<<2048, 256>>>(dst, e);
    k_dinv_alloc<<<(n + 255) / 256, 256>>>(n);
    k_scatter<<<2048, 256>>>(src, dst, e);

    // layer 1
    k_gemm1<<<(n + 127) / 128, 128>>>(x, W1, n);
    k_agg1<<<1184, 256>>>(n);                 // gather + fused BN stats

    k_finalize<<<1, 64>>>(gamma, beta, 1.0f / (float)n);

    // layer 2 (BN + ReLU fused into GEMM2 A-load)
    k_gemm2<<<(n + 127) / 128, 128>>>(W2, n);
    k_agg2<<<1184, 256>>>(n, out, b2);        // gather + fused b2
}